// round 2
// baseline (speedup 1.0000x reference)
#include <cuda_runtime.h>
#include <cuda_bf16.h>

// out[n] = dot(inputs[n, 0:272], weights) + bias
// weights[0:16]   = kernel
// weights[16+x]   = k[4*a1+a2]*k[4*b1+b2]*w1 + k[4*a1+b2]*k[4*b1+a2]*w2
//   where x1=x/16, x2=x%16, a1=x1/4, b1=x1%4, a2=x2/4, b2=x2%4
//
// Streaming GEMV, HBM-bound (544 MB read). Warp-per-row, float4 loads.

#define UNITS 16
#define D 272            // 16 + 256
#define D4 68            // 272 / 4 float4 per row
#define WARPS_PER_BLOCK 8
#define THREADS (WARPS_PER_BLOCK * 32)

__global__ __launch_bounds__(THREADS)
void linear_gemv_kernel(const float* __restrict__ in,
                        const float* __restrict__ kern,
                        const float* __restrict__ w1p,
                        const float* __restrict__ w2p,
                        const float* __restrict__ biasp,
                        float* __restrict__ out,
                        int n)
{
    __shared__ __align__(16) float w[D];

    const int tid = threadIdx.x;

    // Build the 272-float weight vector in shared memory.
    if (tid < UNITS) {
        w[tid] = kern[tid];
    }
    if (tid < 256) {
        const float w1 = *w1p;
        const float w2 = *w2p;
        const int x1 = tid >> 4;
        const int x2 = tid & 15;
        const int a1 = x1 >> 2, b1 = x1 & 3;
        const int a2 = x2 >> 2, b2 = x2 & 3;
        const float k0 = kern[4 * a1 + a2];
        const float k3 = kern[4 * b1 + b2];
        const float k1 = kern[4 * a1 + b2];
        const float k2 = kern[4 * b1 + a2];
        w[UNITS + tid] = k0 * k3 * w1 + k1 * k2 * w2;
    }
    __syncthreads();

    const float bias = *biasp;

    const int lane = tid & 31;
    const int warp_in_block = tid >> 5;
    const long long row = (long long)blockIdx.x * WARPS_PER_BLOCK + warp_in_block;
    if (row >= n) return;

    // Row base: 272 floats = 1088 bytes, 16B-aligned for every row.
    const float4* __restrict__ rp = (const float4*)(in + row * (long long)D);
    const float4* __restrict__ wp = (const float4*)w;

    float sum = 0.0f;

    // 68 float4 per row: lanes cover [0,32), [32,64), tail [64,68) on lanes 0-3.
    {
        float4 a = rp[lane];
        float4 b = wp[lane];
        sum = fmaf(a.x, b.x, sum); sum = fmaf(a.y, b.y, sum);
        sum = fmaf(a.z, b.z, sum); sum = fmaf(a.w, b.w, sum);
    }
    {
        float4 a = rp[lane + 32];
        float4 b = wp[lane + 32];
        sum = fmaf(a.x, b.x, sum); sum = fmaf(a.y, b.y, sum);
        sum = fmaf(a.z, b.z, sum); sum = fmaf(a.w, b.w, sum);
    }
    if (lane < 4) {
        float4 a = rp[lane + 64];
        float4 b = wp[lane + 64];
        sum = fmaf(a.x, b.x, sum); sum = fmaf(a.y, b.y, sum);
        sum = fmaf(a.z, b.z, sum); sum = fmaf(a.w, b.w, sum);
    }

    // Warp tree reduce.
    #pragma unroll
    for (int off = 16; off > 0; off >>= 1)
        sum += __shfl_xor_sync(0xFFFFFFFFu, sum, off);

    if (lane == 0) out[row] = sum + bias;
}

extern "C" void kernel_launch(void* const* d_in, const int* in_sizes, int n_in,
                              void* d_out, int out_size)
{
    const float* in   = (const float*)d_in[0];   // [N, 272]
    const float* kern = (const float*)d_in[1];   // [16]
    const float* w1   = (const float*)d_in[2];   // [1]
    const float* w2   = (const float*)d_in[3];   // [1]
    const float* bias = (const float*)d_in[4];   // [1]
    float* out = (float*)d_out;

    const int n = out_size;  // 500000 rows
    const int blocks = (n + WARPS_PER_BLOCK - 1) / WARPS_PER_BLOCK;

    linear_gemv_kernel<<<blocks, THREADS>>>(in, kern, w1, w2, bias, out, n);
}

// round 3
// speedup vs baseline: 1.0159x; 1.0159x over previous
#include <cuda_runtime.h>
#include <cuda_bf16.h>

// out[n] = dot(inputs[n, 0:272], weights) + bias
// weights[0:16]  = kernel
// weights[16+x]  = k[4a1+a2]*k[4b1+b2]*w1 + k[4a1+b2]*k[4b1+a2]*w2
//
// Streaming GEMV, HBM-bound (544 MB read once). Warp handles 2 rows with all
// 5 LDG.128 front-batched (MLP~5) + non-temporal loads (__ldcs, zero reuse).

#define UNITS 16
#define D 272            // 16 + 256 floats per row
#define WARPS_PER_BLOCK 8
#define THREADS (WARPS_PER_BLOCK * 32)
#define ROWS_PER_WARP 2

__device__ __forceinline__ float4 ldcs4(const float4* p) {
    return __ldcs(p);
}

__global__ __launch_bounds__(THREADS)
void linear_gemv_kernel(const float* __restrict__ in,
                        const float* __restrict__ kern,
                        const float* __restrict__ w1p,
                        const float* __restrict__ w2p,
                        const float* __restrict__ biasp,
                        float* __restrict__ out,
                        int n)
{
    __shared__ __align__(16) float w[D];

    const int tid = threadIdx.x;

    // Build the 272-float weight vector in shared memory.
    if (tid < UNITS) {
        w[tid] = kern[tid];
    }
    if (tid < 256) {
        const float w1 = *w1p;
        const float w2 = *w2p;
        const int x1 = tid >> 4;
        const int x2 = tid & 15;
        const int a1 = x1 >> 2, b1 = x1 & 3;
        const int a2 = x2 >> 2, b2 = x2 & 3;
        w[UNITS + tid] = kern[4 * a1 + a2] * kern[4 * b1 + b2] * w1
                       + kern[4 * a1 + b2] * kern[4 * b1 + a2] * w2;
    }
    __syncthreads();

    const float bias = *biasp;

    const int lane = tid & 31;
    const int warp_in_block = tid >> 5;
    const long long warp_id = (long long)blockIdx.x * WARPS_PER_BLOCK + warp_in_block;
    const long long row0 = warp_id * ROWS_PER_WARP;
    if (row0 >= n) return;
    const bool have_row1 = (row0 + 1) < n;

    const float4* __restrict__ rp0 = (const float4*)(in + row0 * (long long)D);
    const float4* __restrict__ rp1 = (const float4*)(in + (row0 + 1) * (long long)D);
    const float4* __restrict__ wp  = (const float4*)w;

    // ---- Front-batch all global loads (5 independent LDG.128 per lane) ----
    float4 a00 = ldcs4(rp0 + lane);
    float4 a01 = ldcs4(rp0 + lane + 32);
    float4 a10, a11;
    if (have_row1) {
        a10 = ldcs4(rp1 + lane);
        a11 = ldcs4(rp1 + lane + 32);
    }
    // Tail: 4 float4 per row (indices 64..67). Lanes 0-3 -> row0, 4-7 -> row1.
    float4 at = make_float4(0.f, 0.f, 0.f, 0.f);
    if (lane < 4) {
        at = ldcs4(rp0 + 64 + lane);
    } else if (lane < 8 && have_row1) {
        at = ldcs4(rp1 + 64 + (lane - 4));
    }

    // Weights (shared; broadcast-friendly).
    const float4 b0 = wp[lane];
    const float4 b1 = wp[lane + 32];
    float4 bt = make_float4(0.f, 0.f, 0.f, 0.f);
    if (lane < 8) bt = wp[64 + (lane & 3)];

    // ---- FMA reduction ----
    float sum0 = 0.0f, sum1 = 0.0f;
    sum0 = fmaf(a00.x, b0.x, sum0); sum0 = fmaf(a00.y, b0.y, sum0);
    sum0 = fmaf(a00.z, b0.z, sum0); sum0 = fmaf(a00.w, b0.w, sum0);
    sum0 = fmaf(a01.x, b1.x, sum0); sum0 = fmaf(a01.y, b1.y, sum0);
    sum0 = fmaf(a01.z, b1.z, sum0); sum0 = fmaf(a01.w, b1.w, sum0);
    if (have_row1) {
        sum1 = fmaf(a10.x, b0.x, sum1); sum1 = fmaf(a10.y, b0.y, sum1);
        sum1 = fmaf(a10.z, b0.z, sum1); sum1 = fmaf(a10.w, b0.w, sum1);
        sum1 = fmaf(a11.x, b1.x, sum1); sum1 = fmaf(a11.y, b1.y, sum1);
        sum1 = fmaf(a11.z, b1.z, sum1); sum1 = fmaf(a11.w, b1.w, sum1);
    }
    // Tail contributions: lanes 0-3 into sum0, lanes 4-7 into sum1.
    float tsum = fmaf(at.x, bt.x, fmaf(at.y, bt.y, fmaf(at.z, bt.z, at.w * bt.w)));
    if (lane < 4) sum0 += tsum;
    else if (lane < 8) sum1 += tsum;

    // ---- Warp tree reductions ----
    #pragma unroll
    for (int off = 16; off > 0; off >>= 1) {
        sum0 += __shfl_xor_sync(0xFFFFFFFFu, sum0, off);
        sum1 += __shfl_xor_sync(0xFFFFFFFFu, sum1, off);
    }

    if (lane == 0) {
        if (have_row1) {
            float2 o = make_float2(sum0 + bias, sum1 + bias);
            *(float2*)(out + row0) = o;   // rows consecutive, 8B aligned
        } else {
            out[row0] = sum0 + bias;
        }
    }
}

extern "C" void kernel_launch(void* const* d_in, const int* in_sizes, int n_in,
                              void* d_out, int out_size)
{
    const float* in   = (const float*)d_in[0];   // [N, 272]
    const float* kern = (const float*)d_in[1];   // [16]
    const float* w1   = (const float*)d_in[2];   // [1]
    const float* w2   = (const float*)d_in[3];   // [1]
    const float* bias = (const float*)d_in[4];   // [1]
    float* out = (float*)d_out;

    const int n = out_size;  // 500000 rows
    const int rows_per_block = WARPS_PER_BLOCK * ROWS_PER_WARP;
    const int blocks = (n + rows_per_block - 1) / rows_per_block;

    linear_gemv_kernel<<<blocks, THREADS>>>(in, kern, w1, w2, bias, out, n);
}